// round 5
// baseline (speedup 1.0000x reference)
#include <cuda_runtime.h>

#define H_IMG 64
#define W_IMG 64
#define CH    128
#define HD    32
#define HEADS 4
#define KS    3
#define DIL   2
#define KK    9

#define TW 32
#define TH 16
#define NTHREADS (TW*TH)      // 512

#define CPC 8                 // channels staged per stage
#define NSTAGE (HD/CPC)       // 4
#define SH (TH + 4)           // 20 rows (halo 2 each side)
#define SWP 40                // padded row: gx in [tileX-4, tileX+36), float4-aligned
#define SEGS (SWP/4)          // 10 float4 segments per row
#define STAGE_ELEMS (CPC*SH*SEGS)   // 1600 float4 slots
#define SMEM_FLOATS (CPC*SH*SWP)    // 6400 floats = 25.6 KB

__global__ __launch_bounds__(NTHREADS, 3)
void dilate_attn_kernel(const float* __restrict__ q,
                        const float* __restrict__ k,
                        const float* __restrict__ v,
                        float* __restrict__ out)
{
    __shared__ float tile[SMEM_FLOATS];

    const int tx  = threadIdx.x;            // 0..31
    const int ty  = threadIdx.y;            // 0..15
    const int tid = ty * TW + tx;

    const int tilesX = W_IMG / TW;          // 2
    const int tileX = (blockIdx.x % tilesX) * TW;
    const int tileY = (blockIdx.x / tilesX) * TH;
    const int head  = blockIdx.y;
    const int b     = blockIdx.z;

    const int x   = tileX + tx;
    const int y   = tileY + ty;
    const int pix = y * W_IMG + x;

    const float scale = 0.1767766952966369f;   // 32^-0.5

    const size_t plane = (size_t)H_IMG * W_IMG;              // 4096
    const size_t base  = ((size_t)b * CH + head * HD) * plane;

    float logit[KK];
#pragma unroll
    for (int i = 0; i < KK; i++) logit[i] = 0.f;

    // ================= q·k pass: 4 stages of 8 channels =================
    for (int st = 0; st < NSTAGE; st++) {
        const int c0 = st * CPC;
        const float* kbase = k + base + (size_t)c0 * plane;

        // stage 8 k-channel tiles (float4, fully-in/out segments)
#pragma unroll
        for (int ii = 0; ii < 4; ii++) {
            const int i = tid + ii * NTHREADS;
            if (i < STAGE_ELEMS) {
                const int ch  = i / (SH * SEGS);
                const int rem = i - ch * (SH * SEGS);
                const int row = rem / SEGS;
                const int seg = rem - row * SEGS;
                const int gy  = tileY - 2 + row;
                const int gx4 = tileX - 4 + seg * 4;
                float4 val = make_float4(0.f, 0.f, 0.f, 0.f);
                if (gy >= 0 && gy < H_IMG && gx4 >= 0 && gx4 + 3 < W_IMG)
                    val = *reinterpret_cast<const float4*>(
                        kbase + (size_t)ch * plane + gy * W_IMG + gx4);
                *reinterpret_cast<float4*>(&tile[ch * (SH * SWP) + row * SWP + seg * 4]) = val;
            }
        }

        // q values for this stage's channels (independent of smem)
        float qv[CPC];
#pragma unroll
        for (int c = 0; c < CPC; c++)
            qv[c] = __ldg(q + base + (size_t)(c0 + c) * plane + pix);

        __syncthreads();
#pragma unroll
        for (int c = 0; c < CPC; c++) {
            const float* tc = &tile[c * (SH * SWP)];
#pragma unroll
            for (int ki = 0; ki < KS; ki++)
#pragma unroll
                for (int kj = 0; kj < KS; kj++)
                    logit[ki * KS + kj] = fmaf(qv[c],
                        tc[(ty + ki * DIL) * SWP + (tx + kj * DIL + 2)],
                        logit[ki * KS + kj]);
        }
        __syncthreads();
    }

    // ================= softmax over 9 taps =================
    float m = -1e30f;
#pragma unroll
    for (int i = 0; i < KK; i++) {
        logit[i] *= scale;
        m = fmaxf(m, logit[i]);
    }
    float s = 0.f;
    float w[KK];
#pragma unroll
    for (int i = 0; i < KK; i++) {
        w[i] = __expf(logit[i] - m);
        s += w[i];
    }
    const float inv = 1.f / s;
#pragma unroll
    for (int i = 0; i < KK; i++) w[i] *= inv;

    // ================= a·v pass: 4 stages, store 8 channels per stage =================
    float* op = out + ((size_t)b * plane + pix) * CH + head * HD;

    for (int st = 0; st < NSTAGE; st++) {
        const int c0 = st * CPC;
        const float* vbase = v + base + (size_t)c0 * plane;

#pragma unroll
        for (int ii = 0; ii < 4; ii++) {
            const int i = tid + ii * NTHREADS;
            if (i < STAGE_ELEMS) {
                const int ch  = i / (SH * SEGS);
                const int rem = i - ch * (SH * SEGS);
                const int row = rem / SEGS;
                const int seg = rem - row * SEGS;
                const int gy  = tileY - 2 + row;
                const int gx4 = tileX - 4 + seg * 4;
                float4 val = make_float4(0.f, 0.f, 0.f, 0.f);
                if (gy >= 0 && gy < H_IMG && gx4 >= 0 && gx4 + 3 < W_IMG)
                    val = *reinterpret_cast<const float4*>(
                        vbase + (size_t)ch * plane + gy * W_IMG + gx4);
                *reinterpret_cast<float4*>(&tile[ch * (SH * SWP) + row * SWP + seg * 4]) = val;
            }
        }
        __syncthreads();

        float o[CPC];
#pragma unroll
        for (int c = 0; c < CPC; c++) {
            const float* tc = &tile[c * (SH * SWP)];
            float acc = 0.f;
#pragma unroll
            for (int ki = 0; ki < KS; ki++)
#pragma unroll
                for (int kj = 0; kj < KS; kj++)
                    acc = fmaf(w[ki * KS + kj],
                               tc[(ty + ki * DIL) * SWP + (tx + kj * DIL + 2)], acc);
            o[c] = acc;
        }
        __syncthreads();

        // store 8 contiguous output channels: 2 x float4
        float4 t0 = make_float4(o[0], o[1], o[2], o[3]);
        float4 t1 = make_float4(o[4], o[5], o[6], o[7]);
        *reinterpret_cast<float4*>(op + c0)     = t0;
        *reinterpret_cast<float4*>(op + c0 + 4) = t1;
    }
}

extern "C" void kernel_launch(void* const* d_in, const int* in_sizes, int n_in,
                              void* d_out, int out_size)
{
    const float* q = (const float*)d_in[0];
    const float* k = (const float*)d_in[1];
    const float* v = (const float*)d_in[2];
    float* out = (float*)d_out;

    dim3 block(TW, TH);
    dim3 grid((W_IMG / TW) * (H_IMG / TH), HEADS, 16 /*B*/);
    dilate_attn_kernel<<<grid, block>>>(q, k, v, out);
}

// round 6
// speedup vs baseline: 1.2092x; 1.2092x over previous
#include <cuda_runtime.h>

#define H_IMG 64
#define W_IMG 64
#define CH    128
#define HD    32
#define HEADS 4
#define KS    3
#define DIL   2
#define KK    9
#define PLANE 4096            // H*W

#define TW 32
#define TH 16
#define NTHREADS (TW*TH)      // 512

#define CPC 8                 // channels per stage
#define NSTAGE (HD/CPC)       // 4
#define NG 2                  // float4 channel-groups per stage
#define SH (TH + 4)           // 20 rows
#define SW (TW + 4)           // 36 cols (halo 2 each side)
#define CELLS (NG*SH*SW)      // 1440 float4 cells per buffer

// staging: transpose [ch][y][x] global -> [g][row][col][4ch] smem
__device__ __forceinline__ void stage_load(float4* __restrict__ dst,
                                           const float* __restrict__ src,
                                           int tid, int tileX, int tileY)
{
#pragma unroll
    for (int ii = 0; ii < 3; ii++) {
        const int i = tid + ii * NTHREADS;
        if (i < CELLS) {
            const int g   = i / (SH * SW);
            const int rem = i - g * (SH * SW);
            const int row = rem / SW;
            const int col = rem - row * SW;
            const int gy  = tileY - 2 + row;
            const int gx  = tileX - 2 + col;
            float4 val = make_float4(0.f, 0.f, 0.f, 0.f);
            if (gy >= 0 && gy < H_IMG && gx >= 0 && gx < W_IMG) {
                const float* p = src + (size_t)(g * 4) * PLANE + gy * W_IMG + gx;
                val.x = __ldg(p);
                val.y = __ldg(p + PLANE);
                val.z = __ldg(p + 2 * PLANE);
                val.w = __ldg(p + 3 * PLANE);
            }
            dst[i] = val;
        }
    }
}

__device__ __forceinline__ void qk_compute(const float4* __restrict__ buf,
                                           const float* __restrict__ qv,
                                           float* __restrict__ logit,
                                           int tx, int ty)
{
#pragma unroll
    for (int g = 0; g < NG; g++) {
        const float4* tg = buf + g * (SH * SW);
        const float q0 = qv[4 * g + 0], q1 = qv[4 * g + 1];
        const float q2 = qv[4 * g + 2], q3 = qv[4 * g + 3];
#pragma unroll
        for (int ki = 0; ki < KS; ki++)
#pragma unroll
            for (int kj = 0; kj < KS; kj++) {
                const float4 kv = tg[(ty + 2 * ki) * SW + (tx + 2 * kj)];
                const int t = ki * KS + kj;
                float acc = logit[t];
                acc = fmaf(q0, kv.x, acc);
                acc = fmaf(q1, kv.y, acc);
                acc = fmaf(q2, kv.z, acc);
                acc = fmaf(q3, kv.w, acc);
                logit[t] = acc;
            }
    }
}

__device__ __forceinline__ void av_compute(const float4* __restrict__ buf,
                                           const float* __restrict__ w,
                                           float* __restrict__ o,
                                           int tx, int ty)
{
#pragma unroll
    for (int g = 0; g < NG; g++) {
        const float4* tg = buf + g * (SH * SW);
        float a0 = 0.f, a1 = 0.f, a2 = 0.f, a3 = 0.f;
#pragma unroll
        for (int ki = 0; ki < KS; ki++)
#pragma unroll
            for (int kj = 0; kj < KS; kj++) {
                const float4 kv = tg[(ty + 2 * ki) * SW + (tx + 2 * kj)];
                const float wt = w[ki * KS + kj];
                a0 = fmaf(wt, kv.x, a0);
                a1 = fmaf(wt, kv.y, a1);
                a2 = fmaf(wt, kv.z, a2);
                a3 = fmaf(wt, kv.w, a3);
            }
        o[4 * g + 0] = a0; o[4 * g + 1] = a1;
        o[4 * g + 2] = a2; o[4 * g + 3] = a3;
    }
}

__global__ __launch_bounds__(NTHREADS, 2)
void dilate_attn_kernel(const float* __restrict__ q,
                        const float* __restrict__ k,
                        const float* __restrict__ v,
                        float* __restrict__ out)
{
    __shared__ float4 buf[2][CELLS];   // 2 x 22.5 KB

    const int tx  = threadIdx.x;
    const int ty  = threadIdx.y;
    const int tid = ty * TW + tx;

    const int tilesX = W_IMG / TW;          // 2
    const int tileX = (blockIdx.x % tilesX) * TW;
    const int tileY = (blockIdx.x / tilesX) * TH;
    const int head  = blockIdx.y;
    const int b     = blockIdx.z;

    const int x   = tileX + tx;
    const int y   = tileY + ty;
    const int pix = y * W_IMG + x;

    const float scale = 0.1767766952966369f;   // 32^-0.5

    const size_t base = ((size_t)b * CH + head * HD) * PLANE;
    const float* qb = q + base + pix;

    float logit[KK];
#pragma unroll
    for (int i = 0; i < KK; i++) logit[i] = 0.f;

    // ---- prologue: k stage 0 -> buf0, q stage 0 ----
    stage_load(buf[0], k + base, tid, tileX, tileY);
    float qv[CPC];
#pragma unroll
    for (int c = 0; c < CPC; c++) qv[c] = __ldg(qb + (size_t)c * PLANE);

    // ---- q.k pipeline ----
#pragma unroll
    for (int st = 0; st < NSTAGE; st++) {
        __syncthreads();
        if (st + 1 < NSTAGE)
            stage_load(buf[(st + 1) & 1], k + base + (size_t)(st + 1) * CPC * PLANE,
                       tid, tileX, tileY);
        else
            stage_load(buf[(st + 1) & 1], v + base, tid, tileX, tileY); // v stage 0

        // compute current stage from buf[st&1]
        qk_compute(buf[st & 1], qv, logit, tx, ty);

        // preload q for next stage (overlaps with next barrier wait)
        if (st + 1 < NSTAGE) {
#pragma unroll
            for (int c = 0; c < CPC; c++)
                qv[c] = __ldg(qb + (size_t)((st + 1) * CPC + c) * PLANE);
        }
    }

    // ---- softmax over 9 taps (per-thread, no sync needed) ----
    {
        float m = -1e30f;
#pragma unroll
        for (int i = 0; i < KK; i++) {
            logit[i] *= scale;
            m = fmaxf(m, logit[i]);
        }
        float s = 0.f;
#pragma unroll
        for (int i = 0; i < KK; i++) {
            logit[i] = __expf(logit[i] - m);
            s += logit[i];
        }
        const float inv = 1.f / s;
#pragma unroll
        for (int i = 0; i < KK; i++) logit[i] *= inv;   // logit[] now = weights
    }

    // ---- a.v pipeline (v stage 0 already in flight into buf[0]) ----
    float* op = out + ((size_t)b * PLANE + pix) * CH + head * HD;

#pragma unroll
    for (int st = 0; st < NSTAGE; st++) {
        __syncthreads();
        if (st + 1 < NSTAGE)
            stage_load(buf[(st + 1) & 1], v + base + (size_t)(st + 1) * CPC * PLANE,
                       tid, tileX, tileY);

        float o[CPC];
        av_compute(buf[st & 1], logit, o, tx, ty);

        float4 t0 = make_float4(o[0], o[1], o[2], o[3]);
        float4 t1 = make_float4(o[4], o[5], o[6], o[7]);
        *reinterpret_cast<float4*>(op + st * CPC)     = t0;
        *reinterpret_cast<float4*>(op + st * CPC + 4) = t1;
    }
}

extern "C" void kernel_launch(void* const* d_in, const int* in_sizes, int n_in,
                              void* d_out, int out_size)
{
    const float* q = (const float*)d_in[0];
    const float* k = (const float*)d_in[1];
    const float* v = (const float*)d_in[2];
    float* out = (float*)d_out;

    dim3 block(TW, TH);
    dim3 grid((W_IMG / TW) * (H_IMG / TH), HEADS, 16 /*B*/);
    dilate_attn_kernel<<<grid, block>>>(q, k, v, out);
}

// round 8
// speedup vs baseline: 1.4649x; 1.2115x over previous
#include <cuda_runtime.h>
#include <cstdint>

#define H_IMG 64
#define W_IMG 64
#define CH    128
#define HD    32
#define HEADS 4
#define KS    3
#define DIL   2
#define KK    9
#define PLANE 4096

#define TW 32
#define TH 16
#define NTHREADS (TW*TH)       // 512

#define CPC 4                  // channels per stage
#define NST_K 8                // k stages
#define NST   16               // total stages (k then v)
#define SH 20                  // 16 + halo 2 each side
#define SWP 40                 // padded cols: gx in [tileX-4, tileX+36), 16B aligned
#define SEGS 10                // float4 segments per row
#define CELLS (CPC*SH*SEGS)    // 800 cp.async cells per stage
#define STAGE_FLOATS (CPC*SH*SWP)   // 3200
#define RING 3

__device__ __forceinline__ uint32_t s2u(const void* p) {
    return (uint32_t)__cvta_generic_to_shared(p);
}

// issue one stage's 800 16B cp.asyncs (zfill out-of-image); commits a group
__device__ __forceinline__ void issue_stage(const float* __restrict__ src,
                                            float* __restrict__ dst,
                                            int tid, int tileX, int tileY)
{
#pragma unroll
    for (int ii = 0; ii < 2; ii++) {
        const int i = tid + ii * NTHREADS;
        if (i < CELLS) {
            const int ch  = i / (SH * SEGS);
            const int rem = i - ch * (SH * SEGS);
            const int row = rem / SEGS;
            const int seg = rem - row * SEGS;
            const int gy  = tileY - 2 + row;
            const int gx  = tileX - 4 + seg * 4;
            const bool inb = (gy >= 0) & (gy < H_IMG) & (gx >= 0) & (gx < W_IMG);
            const float* gp = inb ? (src + ch * PLANE + gy * W_IMG + gx) : src;
            const int sz = inb ? 16 : 0;
            const uint32_t sa = s2u(dst + ch * (SH * SWP) + row * SWP + seg * 4);
            asm volatile("cp.async.cg.shared.global [%0], [%1], 16, %2;\n"
                         :: "r"(sa), "l"(gp), "r"(sz) : "memory");
        }
    }
    asm volatile("cp.async.commit_group;\n" ::: "memory");
}

#define CP_COMMIT_EMPTY() asm volatile("cp.async.commit_group;\n" ::: "memory")
#define CP_WAIT1() asm volatile("cp.async.wait_group 1;\n" ::: "memory")

__global__ __launch_bounds__(NTHREADS, 2)
void dilate_attn_kernel(const float* __restrict__ q,
                        const float* __restrict__ k,
                        const float* __restrict__ v,
                        float* __restrict__ out)
{
    __shared__ __align__(16) float ring[RING][STAGE_FLOATS];   // 38.4 KB

    const int tx  = threadIdx.x;
    const int ty  = threadIdx.y;
    const int tid = ty * TW + tx;

    const int tilesX = W_IMG / TW;           // 2
    const int tileX = (blockIdx.x % tilesX) * TW;
    const int tileY = (blockIdx.x / tilesX) * TH;
    const int head  = blockIdx.y;
    const int b     = blockIdx.z;

    const int x   = tileX + tx;
    const int y   = tileY + ty;
    const int pix = y * W_IMG + x;

    const float scale = 0.1767766952966369f;  // 32^-0.5

    const size_t base = ((size_t)b * CH + head * HD) * PLANE;
    const float* kb = k + base;
    const float* vb = v + base;
    const float* qb = q + base + pix;

    // prologue: issue stages 0,1 (k channels 0-3, 4-7)
    issue_stage(kb,              ring[0], tid, tileX, tileY);
    issue_stage(kb + 4 * PLANE,  ring[1], tid, tileX, tileY);

    float qcur[CPC], qnxt[CPC];
#pragma unroll
    for (int c = 0; c < CPC; c++) qcur[c] = __ldg(qb + (size_t)c * PLANE);
#pragma unroll
    for (int c = 0; c < CPC; c++) qnxt[c] = __ldg(qb + (size_t)(CPC + c) * PLANE);

    float logit[KK];
#pragma unroll
    for (int i = 0; i < KK; i++) logit[i] = 0.f;

    // ================= q.k stages 0..7 =================
#pragma unroll
    for (int s = 0; s < NST_K; s++) {
        CP_WAIT1();
        __syncthreads();

        // issue stage s+2 (k stages 2..7, then v stages 8,9)
        {
            const int sn = s + 2;
            const float* src = (sn < NST_K) ? (kb + sn * CPC * PLANE)
                                            : (vb + (sn - NST_K) * CPC * PLANE);
            issue_stage(src, ring[sn % RING], tid, tileX, tileY);
        }

        // compute stage s
        const float* tb = ring[s % RING];
#pragma unroll
        for (int c = 0; c < CPC; c++) {
            const float* tc = tb + c * (SH * SWP) + ty * SWP + tx + 2;
            const float qc = qcur[c];
#pragma unroll
            for (int ki = 0; ki < KS; ki++)
#pragma unroll
                for (int kj = 0; kj < KS; kj++)
                    logit[ki * KS + kj] = fmaf(qc, tc[(2 * ki) * SWP + 2 * kj],
                                               logit[ki * KS + kj]);
        }

        // rotate q prefetch (distance 2)
#pragma unroll
        for (int c = 0; c < CPC; c++) qcur[c] = qnxt[c];
        if (s + 2 < NST_K) {
#pragma unroll
            for (int c = 0; c < CPC; c++)
                qnxt[c] = __ldg(qb + (size_t)((s + 2) * CPC + c) * PLANE);
        }
    }

    // ================= softmax over 9 taps =================
    {
        float m = -1e30f;
#pragma unroll
        for (int i = 0; i < KK; i++) {
            logit[i] *= scale;
            m = fmaxf(m, logit[i]);
        }
        float ssum = 0.f;
#pragma unroll
        for (int i = 0; i < KK; i++) {
            logit[i] = __expf(logit[i] - m);
            ssum += logit[i];
        }
        const float inv = 1.f / ssum;
#pragma unroll
        for (int i = 0; i < KK; i++) logit[i] *= inv;   // logit[] = weights now
    }

    // ================= a.v stages 8..15 =================
    float* op = out + ((size_t)b * PLANE + pix) * CH + head * HD;

#pragma unroll
    for (int s = NST_K; s < NST; s++) {
        CP_WAIT1();
        __syncthreads();

        if (s + 2 < NST)
            issue_stage(vb + (s + 2 - NST_K) * CPC * PLANE,
                        ring[(s + 2) % RING], tid, tileX, tileY);
        else
            CP_COMMIT_EMPTY();   // keep group count ahead so CP_WAIT1 drains stage s

        const float* tb = ring[s % RING];
        float o[CPC];
#pragma unroll
        for (int c = 0; c < CPC; c++) {
            const float* tc = tb + c * (SH * SWP) + ty * SWP + tx + 2;
            float acc = 0.f;
#pragma unroll
            for (int ki = 0; ki < KS; ki++)
#pragma unroll
                for (int kj = 0; kj < KS; kj++)
                    acc = fmaf(logit[ki * KS + kj], tc[(2 * ki) * SWP + 2 * kj], acc);
            o[c] = acc;
        }

        *reinterpret_cast<float4*>(op + (s - NST_K) * CPC) =
            make_float4(o[0], o[1], o[2], o[3]);
    }
}

extern "C" void kernel_launch(void* const* d_in, const int* in_sizes, int n_in,
                              void* d_out, int out_size)
{
    const float* q = (const float*)d_in[0];
    const float* k = (const float*)d_in[1];
    const float* v = (const float*)d_in[2];
    float* out = (float*)d_out;

    dim3 block(TW, TH);
    dim3 grid((W_IMG / TW) * (H_IMG / TH), HEADS, 16 /*B*/);
    dilate_attn_kernel<<<grid, block>>>(q, k, v, out);
}